// round 14
// baseline (speedup 1.0000x reference)
#include <cuda_runtime.h>
#include <cuda_fp16.h>
#include <math.h>
#include <stdint.h>

#define NMAX 10000
#define EMAX 160000
#define NCHUNKMAX 4608

// ---------------- weight-half buffer segment offsets (halves) ----------------
#define OFF_W2   0                       // 125*32*64
#define OFF_W3   256000                  // 125*64*64 each
#define OFF_W4   768000
#define OFF_W5   1280000
#define OFF_W6   1792000
#define OFF_R2   2304000                 // 32*64
#define OFF_R3   2306048                 // 64*64 each
#define OFF_R4   2310144
#define OFF_R5   2314240
#define OFF_R6   2318336
#define OFF_FC1  2322432                 // 256*64
#define OFF_FC2  2338816                 // 1024*256
#define WH_TOTAL 2600960

// ---------------- scratch (static device globals; no allocation) ----------------
__device__ __half g_hAh[NMAX * 64];
__device__ __half g_hBh[NMAX * 64];
__device__ __half g_h256h[NMAX * 256];
__device__ float  g_root[NMAX * 64];
__device__ __half g_msgh[EMAX * 64];
__device__ __half g_wh[WH_TOTAL];
__device__ int    g_cellE[EMAX];
__device__ int    g_rankC[EMAX];
__device__ int    g_rankD[EMAX];
__device__ int    g_slotE[EMAX];
__device__ int    g_srcC[EMAX];
__device__ int    g_slotC[EMAX];
__device__ float  g_basisC[EMAX * 8];
__device__ int    g_cellCnt[64];
__device__ int    g_cellStart[65];
__device__ int    g_deg[NMAX];
__device__ int    g_dstStart[NMAX + 1];
__device__ int    g_chunkCell[NCHUNKMAX];
__device__ int    g_chunkBeg[NCHUNKMAX];
__device__ int    g_numChunks;

// ---------------- helpers ----------------
__device__ __forceinline__ uint32_t smem_u32(const void* p) {
    uint32_t a;
    asm("{ .reg .u64 t; cvta.to.shared.u64 t, %1; cvt.u32.u64 %0, t; }" : "=r"(a) : "l"(p));
    return a;
}
__device__ __forceinline__ void cp16(uint32_t sdst, const void* gsrc) {
    asm volatile("cp.async.cg.shared.global [%0], [%1], 16;" :: "r"(sdst), "l"(gsrc));
}
__device__ __forceinline__ void cp16z(uint32_t sdst, const void* gsrc, int sz) {
    asm volatile("cp.async.cg.shared.global [%0], [%1], 16, %2;" :: "r"(sdst), "l"(gsrc), "r"(sz));
}
#define CP_COMMIT() asm volatile("cp.async.commit_group;" ::: "memory")
template <int n> __device__ __forceinline__ void cp_wait() {
    asm volatile("cp.async.wait_group %0;" :: "n"(n) : "memory");
}

__device__ __forceinline__ void mma16816(float* d, uint32_t a0, uint32_t a1, uint32_t a2, uint32_t a3,
                                         uint32_t b0, uint32_t b1) {
    asm volatile(
        "mma.sync.aligned.m16n8k16.row.col.f32.f16.f16.f32 "
        "{%0,%1,%2,%3}, {%4,%5,%6,%7}, {%8,%9}, {%0,%1,%2,%3};"
        : "+f"(d[0]), "+f"(d[1]), "+f"(d[2]), "+f"(d[3])
        : "r"(a0), "r"(a1), "r"(a2), "r"(a3), "r"(b0), "r"(b1));
}
__device__ __forceinline__ uint32_t hscale(uint32_t a, uint32_t s) {
    __half2 r = __hmul2(*reinterpret_cast<__half2*>(&a), *reinterpret_cast<__half2*>(&s));
    return *reinterpret_cast<uint32_t*>(&r);
}
__device__ __forceinline__ uint32_t hbcast(float s) {
    __half2 h = __half2half2(__float2half_rn(s));
    return *reinterpret_cast<uint32_t*>(&h);
}
__device__ __forceinline__ float elu_f(float v) {
    return v > 0.0f ? v : (__expf(v) - 1.0f);
}
__device__ __forceinline__ void basis_of(const float* __restrict__ ps, int e,
                                         float* fr, int* cell) {
#pragma unroll
    for (int d = 0; d < 3; d++) {
        float pos = ps[e * 3 + d] * 4.0f;
        float l = floorf(pos);
        l = fminf(fmaxf(l, 0.0f), 3.0f);
        fr[d] = pos - l;
        if (d == 0) *cell = (int)l * 16;
        else if (d == 1) *cell += (int)l * 4;
        else *cell += (int)l;
    }
}
__device__ __forceinline__ float basis_w(const float* fr, int b) {
    float w = 1.0f;
#pragma unroll
    for (int d = 0; d < 3; d++) w *= ((b >> d) & 1) ? fr[d] : (1.0f - fr[d]);
    return w;
}

// ---------------- init ----------------
__global__ void k_init(int N) {
    int i = blockIdx.x * blockDim.x + threadIdx.x;
    if (i < 64) g_cellCnt[i] = 0;
    if (i < N)  g_deg[i] = 0;
}

// ---------------- prep (edges) + weight convert (extra blocks) ----------------
__device__ __forceinline__ void w2h_seg(const float* src, __half* dst, int K, int NC, int KB,
                                        int i0, int i1, int tid, int stride) {
    for (int i = tid + i0; i < i1; i += stride) {
        int li = i - i0;
        int kb = li / (K * NC);
        int rem = li % (K * NC);
        int n = rem / K, k = rem % K;
        dst[li] = __float2half(src[(size_t)kb * K * NC + (size_t)k * NC + n]);
    }
}
__global__ void __launch_bounds__(256) k_prep(
    const int* __restrict__ ei, const float* __restrict__ ps, int E, int eg,
    const float* w2, const float* w3, const float* w4, const float* w5, const float* w6,
    const float* r2, const float* r3, const float* r4, const float* r5, const float* r6,
    const float* fc1w, const float* fc2w) {
    int b = blockIdx.x;
    if (b < eg) {
        int e = b * 256 + threadIdx.x;
        if (e >= E) return;
        float fr[3];
        int cell;
        basis_of(ps, e, fr, &cell);
        g_cellE[e] = cell;
        g_rankC[e] = atomicAdd(&g_cellCnt[cell], 1);
        g_rankD[e] = atomicAdd(&g_deg[ei[E + e]], 1);
    } else {
        int tid = (b - eg) * 256 + threadIdx.x;
        int stride = (gridDim.x - eg) * 256;
        w2h_seg(w2,  g_wh + OFF_W2, 32, 64, 125, OFF_W2, OFF_W3, tid, stride);
        w2h_seg(w3,  g_wh + OFF_W3, 64, 64, 125, OFF_W3, OFF_W4, tid, stride);
        w2h_seg(w4,  g_wh + OFF_W4, 64, 64, 125, OFF_W4, OFF_W5, tid, stride);
        w2h_seg(w5,  g_wh + OFF_W5, 64, 64, 125, OFF_W5, OFF_W6, tid, stride);
        w2h_seg(w6,  g_wh + OFF_W6, 64, 64, 125, OFF_W6, OFF_R2, tid, stride);
        w2h_seg(r2,  g_wh + OFF_R2, 32, 64, 1, OFF_R2, OFF_R3, tid, stride);
        w2h_seg(r3,  g_wh + OFF_R3, 64, 64, 1, OFF_R3, OFF_R4, tid, stride);
        w2h_seg(r4,  g_wh + OFF_R4, 64, 64, 1, OFF_R4, OFF_R5, tid, stride);
        w2h_seg(r5,  g_wh + OFF_R5, 64, 64, 1, OFF_R5, OFF_R6, tid, stride);
        w2h_seg(r6,  g_wh + OFF_R6, 64, 64, 1, OFF_R6, OFF_FC1, tid, stride);
        w2h_seg(fc1w, g_wh + OFF_FC1, 64, 256, 1, OFF_FC1, OFF_FC2, tid, stride);
        w2h_seg(fc2w, g_wh + OFF_FC2, 256, 1024, 1, OFF_FC2, WH_TOTAL, tid, stride);
    }
}

// ---------------- scan: cell offsets, chunk list (256-edge chunks), degree prefix ----------------
__global__ void __launch_bounds__(1024) k_scan(int N, int E) {
    __shared__ int chOff[64];
    __shared__ int warpSums[32];
    int tid = threadIdx.x;
    if (tid == 0) {
        int s = 0;
        for (int c = 0; c < 64; c++) { g_cellStart[c] = s; s += g_cellCnt[c]; }
        g_cellStart[64] = s;
        int t = 0;
        for (int c = 0; c < 64; c++) { chOff[c] = t; t += (g_cellCnt[c] + 255) / 256; }
        g_numChunks = t;
    }
    __syncthreads();
    if (tid < 64) {
        int t = chOff[tid];
        for (int b = g_cellStart[tid]; b < g_cellStart[tid + 1]; b += 256) {
            g_chunkCell[t] = tid; g_chunkBeg[t] = b; t++;
        }
    }
    int per = (N + 1023) / 1024;
    int base = tid * per;
    int lv[16];
    int s = 0;
#pragma unroll 16
    for (int i = 0; i < 16; i++) {
        if (i >= per) break;
        int v = (base + i < N) ? g_deg[base + i] : 0;
        lv[i] = s; s += v;
    }
    int lane = tid & 31, warp = tid >> 5;
    int incl = s;
#pragma unroll
    for (int off = 1; off < 32; off <<= 1) {
        int t2 = __shfl_up_sync(0xFFFFFFFF, incl, off);
        if (lane >= off) incl += t2;
    }
    if (lane == 31) warpSums[warp] = incl;
    __syncthreads();
    if (warp == 0) {
        int w = (lane < 32) ? warpSums[lane] : 0;
        int wi = w;
#pragma unroll
        for (int off = 1; off < 32; off <<= 1) {
            int t2 = __shfl_up_sync(0xFFFFFFFF, wi, off);
            if (lane >= off) wi += t2;
        }
        warpSums[lane] = wi - w;
    }
    __syncthreads();
    int off0 = warpSums[warp] + (incl - s);
#pragma unroll 16
    for (int i = 0; i < 16; i++) {
        if (i >= per) break;
        if (base + i < N) g_dstStart[base + i] = off0 + lv[i];
    }
    if (tid == 1023) g_dstStart[N] = off0;
}

// ---------------- scatter: basis recomputed from pseudo ----------------
__global__ void k_scatter(const int* __restrict__ ei, const float* __restrict__ ps, int E) {
    int e = blockIdx.x * blockDim.x + threadIdx.x;
    if (e >= E) return;
    int src = ei[e], dst = ei[E + e];
    float fr[3];
    int cell;
    basis_of(ps, e, fr, &cell);
    int p = g_cellStart[cell] + g_rankC[e];
    int q = g_dstStart[dst] + g_rankD[e];
    g_srcC[p] = src;
    g_slotC[p] = q;
    g_slotE[e] = q;
#pragma unroll
    for (int b = 0; b < 8; b++) g_basisC[p * 8 + b] = basis_w(fr, b);
}

// ---------------- fused conv (256-edge chunk, f16 mma, 3-deep W pipeline) + root tail ----------------
template <int CI>
__global__ void __launch_bounds__(256) k_convroot(const __half* __restrict__ xin,
                                                  const __half* __restrict__ Wh,
                                                  const __half* __restrict__ rootw,
                                                  const float* __restrict__ bias,
                                                  float* __restrict__ rootout,
                                                  int M, int nbRoot) {
    constexpr int XPH = (CI == 64) ? 72 : 40;
    constexpr int KP  = XPH;
    constexpr int WCH = 8 * CI;              // 16B chunks per W tile (64 rows x CI/8)
    extern __shared__ char smc[];

    int bi = blockIdx.x;
    int nch = g_numChunks;
    int tid = threadIdx.x, wid = tid >> 5, lid = tid & 31;
    int g = lid >> 2, q = lid & 3;

    if (bi >= nch) {
        // ---------- root path: out[64 rows] = X @ rootw + bias ----------
        int rbIdx = bi - nch;
        if (rbIdx >= nbRoot) return;
        __half* As = (__half*)smc;
        __half* Bs = As + 64 * XPH;
        uint32_t sAs = smem_u32(As), sBs = smem_u32(Bs);
        int rb = rbIdx * 64;
        constexpr int ACH = 8 * CI;
        for (int i = tid; i < ACH; i += 256) {
            int row = i / (CI / 8), c8 = i % (CI / 8);
            int gr = rb + row;
            cp16z(sAs + (row * XPH + c8 * 8) * 2,
                  xin + (size_t)min(gr, M - 1) * CI + c8 * 8, (gr < M) ? 16 : 0);
        }
        for (int i = tid; i < ACH; i += 256) {
            int row = i / (CI / 8), c8 = i % (CI / 8);
            cp16(sBs + (row * KP + c8 * 8) * 2, rootw + row * CI + c8 * 8);
        }
        CP_COMMIT();
        cp_wait<0>();
        __syncthreads();
        if (wid < 4) {
            int wm = wid >> 1, wn = wid & 1;
            float acc[2][4][4];
#pragma unroll
            for (int m = 0; m < 2; m++)
#pragma unroll
                for (int n = 0; n < 4; n++)
#pragma unroll
                    for (int i = 0; i < 4; i++) acc[m][n][i] = 0.0f;
#pragma unroll
            for (int ks = 0; ks < CI / 16; ks++) {
                int k0 = ks * 16;
                uint32_t B0[4], B1[4];
#pragma unroll
                for (int n = 0; n < 4; n++) {
                    int c = wn * 32 + n * 8 + g;
                    B0[n] = *(const uint32_t*)&Bs[c * KP + k0 + 2 * q];
                    B1[n] = *(const uint32_t*)&Bs[c * KP + k0 + 2 * q + 8];
                }
#pragma unroll
                for (int m = 0; m < 2; m++) {
                    int rr = wm * 32 + m * 16 + g;
                    uint32_t a0 = *(const uint32_t*)&As[rr * XPH + k0 + 2 * q];
                    uint32_t a1 = *(const uint32_t*)&As[(rr + 8) * XPH + k0 + 2 * q];
                    uint32_t a2 = *(const uint32_t*)&As[rr * XPH + k0 + 2 * q + 8];
                    uint32_t a3 = *(const uint32_t*)&As[(rr + 8) * XPH + k0 + 2 * q + 8];
#pragma unroll
                    for (int n = 0; n < 4; n++)
                        mma16816(acc[m][n], a0, a1, a2, a3, B0[n], B1[n]);
                }
            }
#pragma unroll
            for (int m = 0; m < 2; m++)
#pragma unroll
                for (int h = 0; h < 2; h++) {
                    int gr = rb + wm * 32 + m * 16 + g + h * 8;
                    if (gr >= M) continue;
#pragma unroll
                    for (int n = 0; n < 4; n++) {
                        int col = wn * 32 + n * 8 + q * 2;
                        float2 bv = *(const float2*)&bias[col];
                        *(float2*)&rootout[(size_t)gr * 64 + col] =
                            make_float2(acc[m][n][h * 2] + bv.x, acc[m][n][h * 2 + 1] + bv.y);
                    }
                }
        }
        return;
    }

    // ---------- conv path: 256-edge chunk; warp = 32 rows x 64 cols ----------
    int*    slots = (int*)smc;                              // 256 ints
    float*  bsm   = (float*)(smc + 1024);                   // 256 x 8
    __half* Xs    = (__half*)(smc + 1024 + 8192);           // 256 x XPH
    __half* Ws    = Xs + 256 * XPH;                         // 3 x 64 x KP

    int cell = g_chunkCell[bi];
    int beg  = g_chunkBeg[bi];
    int R = min(beg + 256, g_cellStart[cell + 1]) - beg;

    int ix = cell >> 4, iy = (cell >> 2) & 3, iz = cell & 3;
    int kbs[8];
#pragma unroll
    for (int b = 0; b < 8; b++)
        kbs[b] = (ix + (b & 1)) * 25 + (iy + ((b >> 1) & 1)) * 5 + (iz + ((b >> 2) & 1));

    uint32_t sXs = smem_u32(Xs), sWs = smem_u32(Ws);

    {   // stage X: one thread per row
        int r = tid;
        bool valid = r < R;
        slots[r] = valid ? g_slotC[beg + r] : -1;
#pragma unroll
        for (int b = 0; b < 8; b++)
            bsm[r * 8 + b] = valid ? g_basisC[(beg + r) * 8 + b] : 0.0f;
        int src = valid ? g_srcC[beg + r] : 0;
        const __half* xp = xin + (size_t)src * CI;
        int sz = valid ? 16 : 0;
#pragma unroll
        for (int i = 0; i < CI / 8; i++)
            cp16z(sXs + (r * XPH + i * 8) * 2, xp + i * 8, sz);
    }
#pragma unroll
    for (int pb = 0; pb < 3; pb++) {
        const __half* wp = Wh + (size_t)kbs[pb] * 64 * CI;
        uint32_t dstb = sWs + (pb * 64 * KP) * 2;
        for (int i = tid; i < WCH; i += 256) {
            int row = i / (CI / 8), c8 = i % (CI / 8);
            cp16(dstb + (row * KP + c8 * 8) * 2, wp + row * CI + c8 * 8);
        }
        CP_COMMIT();
    }

    // warp covers rows [wid*32, wid*32+32), all 64 cols
    float acc[2][8][4];
#pragma unroll
    for (int m = 0; m < 2; m++)
#pragma unroll
        for (int n = 0; n < 8; n++)
#pragma unroll
            for (int i = 0; i < 4; i++) acc[m][n][i] = 0.0f;

#pragma unroll
    for (int b = 0; b < 8; b++) {
        if (b < 6) cp_wait<2>(); else if (b == 6) cp_wait<1>(); else cp_wait<0>();
        __syncthreads();

        const __half* Wb = Ws + (b % 3) * 64 * KP;
        uint32_t hs0[2], hs1[2];
#pragma unroll
        for (int m = 0; m < 2; m++) {
            int rr = wid * 32 + m * 16 + g;
            hs0[m] = hbcast(bsm[rr * 8 + b]);
            hs1[m] = hbcast(bsm[(rr + 8) * 8 + b]);
        }
#pragma unroll
        for (int ks = 0; ks < CI / 16; ks++) {
            int k0 = ks * 16;
            uint32_t B0[8], B1[8];
#pragma unroll
            for (int n = 0; n < 8; n++) {
                int c = n * 8 + g;
                B0[n] = *(const uint32_t*)&Wb[c * KP + k0 + 2 * q];
                B1[n] = *(const uint32_t*)&Wb[c * KP + k0 + 2 * q + 8];
            }
#pragma unroll
            for (int m = 0; m < 2; m++) {
                int rr = wid * 32 + m * 16 + g;
                uint32_t a0 = hscale(*(const uint32_t*)&Xs[rr * XPH + k0 + 2 * q], hs0[m]);
                uint32_t a1 = hscale(*(const uint32_t*)&Xs[(rr + 8) * XPH + k0 + 2 * q], hs1[m]);
                uint32_t a2 = hscale(*(const uint32_t*)&Xs[rr * XPH + k0 + 2 * q + 8], hs0[m]);
                uint32_t a3 = hscale(*(const uint32_t*)&Xs[(rr + 8) * XPH + k0 + 2 * q + 8], hs1[m]);
#pragma unroll
                for (int n = 0; n < 8; n++)
                    mma16816(acc[m][n], a0, a1, a2, a3, B0[n], B1[n]);
            }
        }
        __syncthreads();
        if (b + 3 < 8) {
            const __half* wp = Wh + (size_t)kbs[b + 3] * 64 * CI;
            uint32_t dstb = sWs + ((b % 3) * 64 * KP) * 2;
            for (int i = tid; i < WCH; i += 256) {
                int row = i / (CI / 8), c8 = i % (CI / 8);
                cp16(dstb + (row * KP + c8 * 8) * 2, wp + row * CI + c8 * 8);
            }
            CP_COMMIT();
        }
    }

#pragma unroll
    for (int m = 0; m < 2; m++)
#pragma unroll
        for (int h = 0; h < 2; h++) {
            int row = wid * 32 + m * 16 + g + h * 8;
            int slot = slots[row];
            if (slot >= 0) {
                __half2* base = (__half2*)(g_msgh + (size_t)slot * 64);
#pragma unroll
                for (int n = 0; n < 8; n++)
                    base[(n * 8 + q * 2) >> 1] =
                        __floats2half2_rn(acc[m][n][h * 2], acc[m][n][h * 2 + 1]);
            }
        }
}

// ---------------- layer 1 (CI=1, CO=32): basis recomputed ----------------
__global__ void k_conv1(const float* __restrict__ x, const int* __restrict__ ei,
                        const float* __restrict__ ps, const float* __restrict__ w1, int E) {
    int e = blockIdx.x * 8 + (threadIdx.x >> 5);
    if (e >= E) return;
    int c = threadIdx.x & 31;
    float fr[3];
    int cell;
    basis_of(ps, e, fr, &cell);
    int ix = cell >> 4, iy = (cell >> 2) & 3, iz = cell & 3;
    float acc = 0.0f;
#pragma unroll
    for (int b = 0; b < 8; b++) {
        int kb = (ix + (b & 1)) * 25 + (iy + ((b >> 1) & 1)) * 5 + (iz + ((b >> 2) & 1));
        acc += basis_w(fr, b) * w1[kb * 32 + c];
    }
    g_msgh[(size_t)g_slotE[e] * 32 + c] = __float2half(x[ei[e]] * acc);
}

// ---------------- light reduce (CO=64) ----------------
__global__ void __launch_bounds__(256) k_reduceL(const float* __restrict__ rootb,
                                                 __half* __restrict__ xout, int N) {
    int n = blockIdx.x * 8 + (threadIdx.x >> 5);
    if (n >= N) return;
    int jp = threadIdx.x & 31;
    int s0 = g_dstStart[n], s1 = g_dstStart[n + 1];
    float sx = 0.0f, sy = 0.0f, sx2 = 0.0f, sy2 = 0.0f;
    int r = s0;
    for (; r + 2 <= s1; r += 2) {
        float2 v0 = __half22float2(((const __half2*)(g_msgh + (size_t)r * 64))[jp]);
        float2 v1 = __half22float2(((const __half2*)(g_msgh + (size_t)(r + 1) * 64))[jp]);
        sx += v0.x; sy += v0.y;
        sx2 += v1.x; sy2 += v1.y;
    }
    if (r < s1) {
        float2 v = __half22float2(((const __half2*)(g_msgh + (size_t)r * 64))[jp]);
        sx += v.x; sy += v.y;
    }
    sx += sx2; sy += sy2;
    float inv = 1.0f / (float)max(g_deg[n], 1);
    float2 rb = *(const float2*)&rootb[(size_t)n * 64 + jp * 2];
    ((__half2*)(xout + (size_t)n * 64))[jp] =
        __floats2half2_rn(elu_f(sx * inv + rb.x), elu_f(sy * inv + rb.y));
}

// ---------------- layer-1 reduce (CO=32), root inline ----------------
__global__ void __launch_bounds__(256) k_reduce1(const float* __restrict__ x,
                                                 const float* __restrict__ root1,
                                                 const float* __restrict__ b1,
                                                 __half* __restrict__ xout, int N) {
    int n = blockIdx.x * 16 + (threadIdx.x >> 4);
    if (n >= N) return;
    int jp = threadIdx.x & 15;
    int s0 = g_dstStart[n], s1 = g_dstStart[n + 1];
    float sx = 0.0f, sy = 0.0f;
    for (int r = s0; r < s1; r++) {
        float2 v = __half22float2(((const __half2*)(g_msgh + (size_t)r * 32))[jp]);
        sx += v.x; sy += v.y;
    }
    float inv = 1.0f / (float)max(g_deg[n], 1);
    float xn = x[n];
    float2 rv = *(const float2*)&root1[jp * 2];
    float2 bv = *(const float2*)&b1[jp * 2];
    ((__half2*)(xout + (size_t)n * 32))[jp] =
        __floats2half2_rn(elu_f(sx * inv + xn * rv.x + bv.x), elu_f(sy * inv + xn * rv.y + bv.y));
}

// ---------------- FC GEMM f16: block 64x128, warp 32x32, pipelined ----------------
template <int KD, bool DOELU, bool OUTH>
__global__ void __launch_bounds__(256) k_fc_h(const __half* __restrict__ A,
                                              const __half* __restrict__ Bh,
                                              const float* __restrict__ bias,
                                              void* __restrict__ Cv, int M, int NC) {
    constexpr int APH = 72, BPH = 72;
    constexpr int NIT = KD / 64;
    extern __shared__ char smc[];
    __half* As = (__half*)smc;
    __half* Bs = As + 2 * 64 * APH;
    uint32_t sAs = smem_u32(As), sBs = smem_u32(Bs);
    int rb = blockIdx.x * 64, cb = blockIdx.y * 128;
    int tid = threadIdx.x, wid = tid >> 5, lid = tid & 31;
    int wm = wid >> 2, wn = wid & 3;
    int g = lid >> 2, q = lid & 3;

    auto stage = [&](int it, int buf) {
        int kc = it * 64;
        for (int i = tid; i < 512; i += 256) {
            int row = i >> 3, c8 = i & 7;
            int gr = rb + row;
            cp16z(sAs + (buf * 64 * APH + row * APH + c8 * 8) * 2,
                  A + (size_t)min(gr, M - 1) * KD + kc + c8 * 8, (gr < M) ? 16 : 0);
        }
        for (int i = tid; i < 1024; i += 256) {
            int row = i >> 3, c8 = i & 7;
            cp16(sBs + (buf * 128 * BPH + row * BPH + c8 * 8) * 2,
                 Bh + (size_t)(cb + row) * KD + kc + c8 * 8);
        }
        CP_COMMIT();
    };

    float acc[2][4][4];
#pragma unroll
    for (int m = 0; m < 2; m++)
#pragma unroll
        for (int n = 0; n < 4; n++)
#pragma unroll
            for (int i = 0; i < 4; i++) acc[m][n][i] = 0.0f;

    stage(0, 0);
    if (NIT > 1) stage(1, 1);

#pragma unroll
    for (int it = 0; it < NIT; it++) {
        if (it + 1 < NIT) cp_wait<1>(); else cp_wait<0>();
        __syncthreads();
        const __half* Ab = As + (it & 1) * 64 * APH;
        const __half* Bb = Bs + (it & 1) * 128 * BPH;
#pragma unroll
        for (int ks = 0; ks < 4; ks++) {
            int k0 = ks * 16;
            uint32_t B0[4], B1[4];
#pragma unroll
            for (int n = 0; n < 4; n++) {
                int c = wn * 32 + n * 8 + g;
                B0[n] = *(const uint32_t*)&Bb[c * BPH + k0 + 2 * q];
                B1[n] = *(const uint32_t*)&Bb[c * BPH + k0 + 2 * q + 8];
            }
#pragma unroll
            for (int m = 0; m < 2; m++) {
                int rr = wm * 32 + m * 16 + g;
                uint32_t a0 = *(const uint32_t*)&Ab[rr * APH + k0 + 2 * q];
                uint32_t a1 = *(const uint32_t*)&Ab[(rr + 8) * APH + k0 + 2 * q];
                uint32_t a2 = *(const uint32_t*)&Ab[rr * APH + k0 + 2 * q + 8];
                uint32_t a3 = *(const uint32_t*)&Ab[(rr + 8) * APH + k0 + 2 * q + 8];
#pragma unroll
                for (int n = 0; n < 4; n++)
                    mma16816(acc[m][n], a0, a1, a2, a3, B0[n], B1[n]);
            }
        }
        __syncthreads();
        if (it + 2 < NIT) stage(it + 2, it & 1);
    }

#pragma unroll
    for (int m = 0; m < 2; m++)
#pragma unroll
        for (int h = 0; h < 2; h++) {
            int gr = rb + wm * 32 + m * 16 + g + h * 8;
            if (gr >= M) continue;
#pragma unroll
            for (int n = 0; n < 4; n++) {
                int col = cb + wn * 32 + n * 8 + q * 2;
                float v0 = acc[m][n][h * 2] + bias[col];
                float v1 = acc[m][n][h * 2 + 1] + bias[col + 1];
                if (DOELU) { v0 = elu_f(v0); v1 = elu_f(v1); }
                if (OUTH) {
                    *(__half2*)((__half*)Cv + (size_t)gr * NC + col) = __floats2half2_rn(v0, v1);
                } else {
                    *(float2*)((float*)Cv + (size_t)gr * NC + col) = make_float2(v0, v1);
                }
            }
        }
}

// ---------------- log_softmax ----------------
__global__ void k_lsm(float* __restrict__ out) {
    __shared__ float red[256];
    int n = blockIdx.x;
    float* row = out + (size_t)n * 1024;
    int tid = threadIdx.x;
    float v[4];
    float m = -INFINITY;
#pragma unroll
    for (int i = 0; i < 4; i++) { v[i] = row[tid + 256 * i]; m = fmaxf(m, v[i]); }
    red[tid] = m;
    __syncthreads();
    for (int off = 128; off; off >>= 1) {
        if (tid < off) red[tid] = fmaxf(red[tid], red[tid + off]);
        __syncthreads();
    }
    m = red[0];
    __syncthreads();
    float s = 0.0f;
#pragma unroll
    for (int i = 0; i < 4; i++) s += __expf(v[i] - m);
    red[tid] = s;
    __syncthreads();
    for (int off = 128; off; off >>= 1) {
        if (tid < off) red[tid] += red[tid + off];
        __syncthreads();
    }
    float l = m + __logf(red[0]);
#pragma unroll
    for (int i = 0; i < 4; i++) row[tid + 256 * i] = v[i] - l;
}

// ---------------- launcher ----------------
extern "C" void kernel_launch(void* const* d_in, const int* in_sizes, int n_in,
                              void* d_out, int out_size) {
    const float* x      = (const float*)d_in[0];
    const int*   ei     = (const int*)d_in[1];
    const float* pseudo = (const float*)d_in[2];
    const float *w[6], *root[6], *bias[6];
    for (int i = 0; i < 6; i++) {
        w[i]    = (const float*)d_in[3 + 3 * i];
        root[i] = (const float*)d_in[4 + 3 * i];
        bias[i] = (const float*)d_in[5 + 3 * i];
    }
    const float* fc1b = (const float*)d_in[22];
    const float* fc2b = (const float*)d_in[24];
    float* out = (float*)d_out;

    int N = in_sizes[0];
    int E = in_sizes[1] / 2;

    int eg = (E + 255) / 256;
    int ng = (N + 255) / 256;
    int nchunksUB = (E + 255) / 256 + 64;
    int nb64 = (N + 63) / 64;
    int cgrid = nchunksUB + nb64;

    __half* hAh = nullptr;  cudaGetSymbolAddress((void**)&hAh, g_hAh);
    __half* hBh = nullptr;  cudaGetSymbolAddress((void**)&hBh, g_hBh);
    __half* h256h = nullptr; cudaGetSymbolAddress((void**)&h256h, g_h256h);
    float*  rtb = nullptr;  cudaGetSymbolAddress((void**)&rtb, g_root);
    __half* wh = nullptr;   cudaGetSymbolAddress((void**)&wh, g_wh);

    constexpr int CSM64 = 1024 + 8192 + (256 * 72 + 3 * 64 * 72) * 2;  // 73728
    constexpr int CSM32 = 1024 + 8192 + (256 * 40 + 3 * 64 * 40) * 2;  // 45056
    constexpr int FSM   = (2 * 64 * 72 + 2 * 128 * 72) * 2;            // 55296
    cudaFuncSetAttribute(k_convroot<64>, cudaFuncAttributeMaxDynamicSharedMemorySize, CSM64);
    cudaFuncSetAttribute(k_convroot<32>, cudaFuncAttributeMaxDynamicSharedMemorySize, CSM32);
    cudaFuncSetAttribute((const void*)k_fc_h<64, true, true>, cudaFuncAttributeMaxDynamicSharedMemorySize, FSM);
    cudaFuncSetAttribute((const void*)k_fc_h<256, false, false>, cudaFuncAttributeMaxDynamicSharedMemorySize, FSM);

    k_init<<<ng, 256>>>(N);
    k_prep<<<eg + 160, 256>>>(ei, pseudo, E, eg,
                              w[1], w[2], w[3], w[4], w[5],
                              root[1], root[2], root[3], root[4], root[5],
                              (const float*)d_in[21], (const float*)d_in[23]);
    k_scan<<<1, 1024>>>(N, E);
    k_scatter<<<eg, 256>>>(ei, pseudo, E);

    // layer 1: 1 -> 32
    k_conv1<<<(E + 7) / 8, 256>>>(x, ei, pseudo, w[0], E);
    k_reduce1<<<(N + 15) / 16, 256>>>(x, root[0], bias[0], hAh, N);
    // layer 2: 32 -> 64
    k_convroot<32><<<cgrid, 256, CSM32>>>(hAh, wh + OFF_W2, wh + OFF_R2, bias[1], rtb, N, nb64);
    k_reduceL<<<(N + 7) / 8, 256>>>(rtb, hBh, N);
    // layers 3-6: 64 -> 64
    k_convroot<64><<<cgrid, 256, CSM64>>>(hBh, wh + OFF_W3, wh + OFF_R3, bias[2], rtb, N, nb64);
    k_reduceL<<<(N + 7) / 8, 256>>>(rtb, hAh, N);

    k_convroot<64><<<cgrid, 256, CSM64>>>(hAh, wh + OFF_W4, wh + OFF_R4, bias[3], rtb, N, nb64);
    k_reduceL<<<(N + 7) / 8, 256>>>(rtb, hBh, N);

    k_convroot<64><<<cgrid, 256, CSM64>>>(hBh, wh + OFF_W5, wh + OFF_R5, bias[4], rtb, N, nb64);
    k_reduceL<<<(N + 7) / 8, 256>>>(rtb, hAh, N);

    k_convroot<64><<<cgrid, 256, CSM64>>>(hAh, wh + OFF_W6, wh + OFF_R6, bias[5], rtb, N, nb64);
    k_reduceL<<<(N + 7) / 8, 256>>>(rtb, hBh, N);

    // fc1: [N,64] @ [64,256] + ELU -> half
    k_fc_h<64, true, true><<<dim3(nb64, 2), 256, FSM>>>(hBh, wh + OFF_FC1, fc1b, h256h, N, 256);
    // fc2: [N,256] @ [256,1024] -> fp32 logits
    k_fc_h<256, false, false><<<dim3(nb64, 8), 256, FSM>>>(h256h, wh + OFF_FC2, fc2b, out, N, 1024);
    // log_softmax in place
    k_lsm<<<N, 256>>>(out);
}

// round 17
// speedup vs baseline: 1.0215x; 1.0215x over previous
#include <cuda_runtime.h>
#include <cuda_fp16.h>
#include <math.h>
#include <stdint.h>

#define NMAX 10000
#define EMAX 160000
#define NCHUNKMAX 4608

// ---------------- weight-half buffer segment offsets (halves) ----------------
#define OFF_W2   0                       // 125*32*64
#define OFF_W3   256000                  // 125*64*64 each
#define OFF_W4   768000
#define OFF_W5   1280000
#define OFF_W6   1792000
#define OFF_R2   2304000                 // 32*64
#define OFF_R3   2306048                 // 64*64 each
#define OFF_R4   2310144
#define OFF_R5   2314240
#define OFF_R6   2318336
#define OFF_FC1  2322432                 // 256*64
#define OFF_FC2  2338816                 // 1024*256
#define WH_TOTAL 2600960

// ---------------- scratch (static device globals; no allocation) ----------------
__device__ __half g_hAh[NMAX * 64];
__device__ __half g_hBh[NMAX * 64];
__device__ __half g_h256h[NMAX * 256];
__device__ float  g_root[NMAX * 64];
__device__ __half g_msgh[EMAX * 64];
__device__ __half g_wh[WH_TOTAL];
__device__ int    g_cellE[EMAX];
__device__ int    g_rankC[EMAX];
__device__ int    g_rankD[EMAX];
__device__ int    g_slotE[EMAX];
__device__ int    g_srcC[EMAX];
__device__ int    g_slotC[EMAX];
__device__ float  g_basisC[EMAX * 8];
__device__ int    g_cellCnt[64];
__device__ int    g_cellStart[65];
__device__ int    g_deg[NMAX];
__device__ int    g_dstStart[NMAX + 1];
__device__ int    g_chunkCell[NCHUNKMAX];
__device__ int    g_chunkBeg[NCHUNKMAX];
__device__ int    g_numChunks;

// ---------------- helpers ----------------
__device__ __forceinline__ uint32_t smem_u32(const void* p) {
    uint32_t a;
    asm("{ .reg .u64 t; cvta.to.shared.u64 t, %1; cvt.u32.u64 %0, t; }" : "=r"(a) : "l"(p));
    return a;
}
__device__ __forceinline__ void cp16(uint32_t sdst, const void* gsrc) {
    asm volatile("cp.async.cg.shared.global [%0], [%1], 16;" :: "r"(sdst), "l"(gsrc));
}
__device__ __forceinline__ void cp16z(uint32_t sdst, const void* gsrc, int sz) {
    asm volatile("cp.async.cg.shared.global [%0], [%1], 16, %2;" :: "r"(sdst), "l"(gsrc), "r"(sz));
}
#define CP_COMMIT() asm volatile("cp.async.commit_group;" ::: "memory")
template <int n> __device__ __forceinline__ void cp_wait() {
    asm volatile("cp.async.wait_group %0;" :: "n"(n) : "memory");
}

__device__ __forceinline__ void mma16816(float* d, uint32_t a0, uint32_t a1, uint32_t a2, uint32_t a3,
                                         uint32_t b0, uint32_t b1) {
    asm volatile(
        "mma.sync.aligned.m16n8k16.row.col.f32.f16.f16.f32 "
        "{%0,%1,%2,%3}, {%4,%5,%6,%7}, {%8,%9}, {%0,%1,%2,%3};"
        : "+f"(d[0]), "+f"(d[1]), "+f"(d[2]), "+f"(d[3])
        : "r"(a0), "r"(a1), "r"(a2), "r"(a3), "r"(b0), "r"(b1));
}
__device__ __forceinline__ uint32_t hscale(uint32_t a, uint32_t s) {
    __half2 r = __hmul2(*reinterpret_cast<__half2*>(&a), *reinterpret_cast<__half2*>(&s));
    return *reinterpret_cast<uint32_t*>(&r);
}
__device__ __forceinline__ uint32_t hbcast(float s) {
    __half2 h = __half2half2(__float2half_rn(s));
    return *reinterpret_cast<uint32_t*>(&h);
}
__device__ __forceinline__ float elu_f(float v) {
    return v > 0.0f ? v : (__expf(v) - 1.0f);
}
__device__ __forceinline__ void basis_of(const float* __restrict__ ps, int e,
                                         float* fr, int* cell) {
#pragma unroll
    for (int d = 0; d < 3; d++) {
        float pos = ps[e * 3 + d] * 4.0f;
        float l = floorf(pos);
        l = fminf(fmaxf(l, 0.0f), 3.0f);
        fr[d] = pos - l;
        if (d == 0) *cell = (int)l * 16;
        else if (d == 1) *cell += (int)l * 4;
        else *cell += (int)l;
    }
}
__device__ __forceinline__ float basis_w(const float* fr, int b) {
    float w = 1.0f;
#pragma unroll
    for (int d = 0; d < 3; d++) w *= ((b >> d) & 1) ? fr[d] : (1.0f - fr[d]);
    return w;
}

// ---------------- init ----------------
__global__ void k_init(int N) {
    int i = blockIdx.x * blockDim.x + threadIdx.x;
    if (i < 64) g_cellCnt[i] = 0;
    if (i < N)  g_deg[i] = 0;
}

// ---------------- prep (edges) + weight convert (extra blocks) ----------------
__device__ __forceinline__ void w2h_seg(const float* src, __half* dst, int K, int NC, int KB,
                                        int i0, int i1, int tid, int stride) {
    for (int i = tid + i0; i < i1; i += stride) {
        int li = i - i0;
        int kb = li / (K * NC);
        int rem = li % (K * NC);
        int n = rem / K, k = rem % K;
        dst[li] = __float2half(src[(size_t)kb * K * NC + (size_t)k * NC + n]);
    }
}
__global__ void __launch_bounds__(256) k_prep(
    const int* __restrict__ ei, const float* __restrict__ ps, int E, int eg,
    const float* w2, const float* w3, const float* w4, const float* w5, const float* w6,
    const float* r2, const float* r3, const float* r4, const float* r5, const float* r6,
    const float* fc1w, const float* fc2w) {
    int b = blockIdx.x;
    if (b < eg) {
        int e = b * 256 + threadIdx.x;
        if (e >= E) return;
        float fr[3];
        int cell;
        basis_of(ps, e, fr, &cell);
        g_cellE[e] = cell;
        g_rankC[e] = atomicAdd(&g_cellCnt[cell], 1);
        g_rankD[e] = atomicAdd(&g_deg[ei[E + e]], 1);
    } else {
        int tid = (b - eg) * 256 + threadIdx.x;
        int stride = (gridDim.x - eg) * 256;
        w2h_seg(w2,  g_wh + OFF_W2, 32, 64, 125, OFF_W2, OFF_W3, tid, stride);
        w2h_seg(w3,  g_wh + OFF_W3, 64, 64, 125, OFF_W3, OFF_W4, tid, stride);
        w2h_seg(w4,  g_wh + OFF_W4, 64, 64, 125, OFF_W4, OFF_W5, tid, stride);
        w2h_seg(w5,  g_wh + OFF_W5, 64, 64, 125, OFF_W5, OFF_W6, tid, stride);
        w2h_seg(w6,  g_wh + OFF_W6, 64, 64, 125, OFF_W6, OFF_R2, tid, stride);
        w2h_seg(r2,  g_wh + OFF_R2, 32, 64, 1, OFF_R2, OFF_R3, tid, stride);
        w2h_seg(r3,  g_wh + OFF_R3, 64, 64, 1, OFF_R3, OFF_R4, tid, stride);
        w2h_seg(r4,  g_wh + OFF_R4, 64, 64, 1, OFF_R4, OFF_R5, tid, stride);
        w2h_seg(r5,  g_wh + OFF_R5, 64, 64, 1, OFF_R5, OFF_R6, tid, stride);
        w2h_seg(r6,  g_wh + OFF_R6, 64, 64, 1, OFF_R6, OFF_FC1, tid, stride);
        w2h_seg(fc1w, g_wh + OFF_FC1, 64, 256, 1, OFF_FC1, OFF_FC2, tid, stride);
        w2h_seg(fc2w, g_wh + OFF_FC2, 256, 1024, 1, OFF_FC2, WH_TOTAL, tid, stride);
    }
}

// ---------------- scan: cell offsets, chunk list (128-edge chunks), degree prefix ----------------
__global__ void __launch_bounds__(1024) k_scan(int N, int E) {
    __shared__ int chOff[64];
    __shared__ int warpSums[32];
    int tid = threadIdx.x;
    if (tid == 0) {
        int s = 0;
        for (int c = 0; c < 64; c++) { g_cellStart[c] = s; s += g_cellCnt[c]; }
        g_cellStart[64] = s;
        int t = 0;
        for (int c = 0; c < 64; c++) { chOff[c] = t; t += (g_cellCnt[c] + 127) / 128; }
        g_numChunks = t;
    }
    __syncthreads();
    if (tid < 64) {
        int t = chOff[tid];
        for (int b = g_cellStart[tid]; b < g_cellStart[tid + 1]; b += 128) {
            g_chunkCell[t] = tid; g_chunkBeg[t] = b; t++;
        }
    }
    int per = (N + 1023) / 1024;
    int base = tid * per;
    int lv[16];
    int s = 0;
#pragma unroll 16
    for (int i = 0; i < 16; i++) {
        if (i >= per) break;
        int v = (base + i < N) ? g_deg[base + i] : 0;
        lv[i] = s; s += v;
    }
    int lane = tid & 31, warp = tid >> 5;
    int incl = s;
#pragma unroll
    for (int off = 1; off < 32; off <<= 1) {
        int t2 = __shfl_up_sync(0xFFFFFFFF, incl, off);
        if (lane >= off) incl += t2;
    }
    if (lane == 31) warpSums[warp] = incl;
    __syncthreads();
    if (warp == 0) {
        int w = (lane < 32) ? warpSums[lane] : 0;
        int wi = w;
#pragma unroll
        for (int off = 1; off < 32; off <<= 1) {
            int t2 = __shfl_up_sync(0xFFFFFFFF, wi, off);
            if (lane >= off) wi += t2;
        }
        warpSums[lane] = wi - w;
    }
    __syncthreads();
    int off0 = warpSums[warp] + (incl - s);
#pragma unroll 16
    for (int i = 0; i < 16; i++) {
        if (i >= per) break;
        if (base + i < N) g_dstStart[base + i] = off0 + lv[i];
    }
    if (tid == 1023) g_dstStart[N] = off0;
}

// ---------------- scatter: basis recomputed, vectorized basis store ----------------
__global__ void k_scatter(const int* __restrict__ ei, const float* __restrict__ ps, int E) {
    int e = blockIdx.x * blockDim.x + threadIdx.x;
    if (e >= E) return;
    int src = ei[e], dst = ei[E + e];
    float fr[3];
    int cell;
    basis_of(ps, e, fr, &cell);
    int p = g_cellStart[cell] + g_rankC[e];
    int q = g_dstStart[dst] + g_rankD[e];
    g_srcC[p] = src;
    g_slotC[p] = q;
    g_slotE[e] = q;
    float4 b0 = make_float4(basis_w(fr, 0), basis_w(fr, 1), basis_w(fr, 2), basis_w(fr, 3));
    float4 b1 = make_float4(basis_w(fr, 4), basis_w(fr, 5), basis_w(fr, 6), basis_w(fr, 7));
    *(float4*)&g_basisC[p * 8]     = b0;
    *(float4*)&g_basisC[p * 8 + 4] = b1;
}

// ---------------- fused conv (128-edge chunk, f16 mma, 3-deep W pipeline) + root tail ----------------
template <int CI>
__global__ void __launch_bounds__(256) k_convroot(const __half* __restrict__ xin,
                                                  const __half* __restrict__ Wh,
                                                  const __half* __restrict__ rootw,
                                                  const float* __restrict__ bias,
                                                  float* __restrict__ rootout,
                                                  int M, int nbRoot) {
    constexpr int XPH = (CI == 64) ? 72 : 40;
    constexpr int KP  = XPH;
    constexpr int XROWCH = CI / 16;
    constexpr int WCH = 8 * CI;
    extern __shared__ char smc[];

    int bi = blockIdx.x;
    int nch = g_numChunks;
    int tid = threadIdx.x, wid = tid >> 5, lid = tid & 31;
    int g = lid >> 2, q = lid & 3;

    if (bi >= nch) {
        // ---------- root path ----------
        int rbIdx = bi - nch;
        if (rbIdx >= nbRoot) return;
        __half* As = (__half*)smc;
        __half* Bs = As + 64 * XPH;
        uint32_t sAs = smem_u32(As), sBs = smem_u32(Bs);
        int rb = rbIdx * 64;
        constexpr int ACH = 8 * CI;
        for (int i = tid; i < ACH; i += 256) {
            int row = i / (CI / 8), c8 = i % (CI / 8);
            int gr = rb + row;
            cp16z(sAs + (row * XPH + c8 * 8) * 2,
                  xin + (size_t)min(gr, M - 1) * CI + c8 * 8, (gr < M) ? 16 : 0);
        }
        for (int i = tid; i < ACH; i += 256) {
            int row = i / (CI / 8), c8 = i % (CI / 8);
            cp16(sBs + (row * KP + c8 * 8) * 2, rootw + row * CI + c8 * 8);
        }
        CP_COMMIT();
        cp_wait<0>();
        __syncthreads();
        if (wid < 4) {
            int wm = wid >> 1, wn = wid & 1;
            float acc[2][4][4];
#pragma unroll
            for (int m = 0; m < 2; m++)
#pragma unroll
                for (int n = 0; n < 4; n++)
#pragma unroll
                    for (int i = 0; i < 4; i++) acc[m][n][i] = 0.0f;
#pragma unroll
            for (int ks = 0; ks < CI / 16; ks++) {
                int k0 = ks * 16;
                uint32_t B0[4], B1[4];
#pragma unroll
                for (int n = 0; n < 4; n++) {
                    int c = wn * 32 + n * 8 + g;
                    B0[n] = *(const uint32_t*)&Bs[c * KP + k0 + 2 * q];
                    B1[n] = *(const uint32_t*)&Bs[c * KP + k0 + 2 * q + 8];
                }
#pragma unroll
                for (int m = 0; m < 2; m++) {
                    int rr = wm * 32 + m * 16 + g;
                    uint32_t a0 = *(const uint32_t*)&As[rr * XPH + k0 + 2 * q];
                    uint32_t a1 = *(const uint32_t*)&As[(rr + 8) * XPH + k0 + 2 * q];
                    uint32_t a2 = *(const uint32_t*)&As[rr * XPH + k0 + 2 * q + 8];
                    uint32_t a3 = *(const uint32_t*)&As[(rr + 8) * XPH + k0 + 2 * q + 8];
#pragma unroll
                    for (int n = 0; n < 4; n++)
                        mma16816(acc[m][n], a0, a1, a2, a3, B0[n], B1[n]);
                }
            }
#pragma unroll
            for (int m = 0; m < 2; m++)
#pragma unroll
                for (int h = 0; h < 2; h++) {
                    int gr = rb + wm * 32 + m * 16 + g + h * 8;
                    if (gr >= M) continue;
#pragma unroll
                    for (int n = 0; n < 4; n++) {
                        int col = wn * 32 + n * 8 + q * 2;
                        float2 bv = *(const float2*)&bias[col];
                        *(float2*)&rootout[(size_t)gr * 64 + col] =
                            make_float2(acc[m][n][h * 2] + bv.x, acc[m][n][h * 2 + 1] + bv.y);
                    }
                }
        }
        return;
    }

    // ---------- conv path (3 W buffers, prefetch depth 2) ----------
    int*    slots = (int*)smc;
    float*  bsm   = (float*)(smc + 512);
    __half* Xs    = (__half*)(smc + 512 + 4096);
    __half* Ws    = Xs + 128 * XPH;          // 3 x 64 x KP

    int cell = g_chunkCell[bi];
    int beg  = g_chunkBeg[bi];
    int R = min(beg + 128, g_cellStart[cell + 1]) - beg;

    int ix = cell >> 4, iy = (cell >> 2) & 3, iz = cell & 3;
    int kbs[8];
#pragma unroll
    for (int b = 0; b < 8; b++)
        kbs[b] = (ix + (b & 1)) * 25 + (iy + ((b >> 1) & 1)) * 5 + (iz + ((b >> 2) & 1));

    uint32_t sXs = smem_u32(Xs), sWs = smem_u32(Ws);

    {   // group 0: X + W[corner0]
        int r = tid >> 1, half = tid & 1;
        bool valid = r < R;
        if (half == 0) {
            slots[r] = valid ? g_slotC[beg + r] : -1;
#pragma unroll
            for (int b = 0; b < 8; b++)
                bsm[r * 8 + b] = valid ? g_basisC[(size_t)(beg + r) * 8 + b] : 0.0f;
        }
        int src = valid ? g_srcC[beg + r] : 0;
        const __half* xp = xin + (size_t)src * CI + half * (CI / 2);
        int sz = valid ? 16 : 0;
#pragma unroll
        for (int i = 0; i < XROWCH; i++)
            cp16z(sXs + (r * XPH + half * (CI / 2) + i * 8) * 2, xp + i * 8, sz);
    }
#pragma unroll
    for (int pb = 0; pb < 3; pb++) {
        const __half* wp = Wh + (size_t)kbs[pb] * 64 * CI;
        uint32_t dstb = sWs + (pb * 64 * KP) * 2;
        for (int i = tid; i < WCH; i += 256) {
            int row = i / (CI / 8), c8 = i % (CI / 8);
            cp16(dstb + (row * KP + c8 * 8) * 2, wp + row * CI + c8 * 8);
        }
        CP_COMMIT();
    }

    int wm = wid >> 1, wn = wid & 1;
    float acc[2][4][4];
#pragma unroll
    for (int m = 0; m < 2; m++)
#pragma unroll
        for (int n = 0; n < 4; n++)
#pragma unroll
            for (int i = 0; i < 4; i++) acc[m][n][i] = 0.0f;

#pragma unroll
    for (int b = 0; b < 8; b++) {
        if (b < 6) cp_wait<2>(); else if (b == 6) cp_wait<1>(); else cp_wait<0>();
        __syncthreads();

        const __half* Wb = Ws + (b % 3) * 64 * KP;
        uint32_t hs0[2], hs1[2];
#pragma unroll
        for (int m = 0; m < 2; m++) {
            int rr = wm * 32 + m * 16 + g;
            hs0[m] = hbcast(bsm[rr * 8 + b]);
            hs1[m] = hbcast(bsm[(rr + 8) * 8 + b]);
        }
#pragma unroll
        for (int ks = 0; ks < CI / 16; ks++) {
            int k0 = ks * 16;
            uint32_t B0[4], B1[4];
#pragma unroll
            for (int n = 0; n < 4; n++) {
                int c = wn * 32 + n * 8 + g;
                B0[n] = *(const uint32_t*)&Wb[c * KP + k0 + 2 * q];
                B1[n] = *(const uint32_t*)&Wb[c * KP + k0 + 2 * q + 8];
            }
#pragma unroll
            for (int m = 0; m < 2; m++) {
                int rr = wm * 32 + m * 16 + g;
                uint32_t a0 = hscale(*(const uint32_t*)&Xs[rr * XPH + k0 + 2 * q], hs0[m]);
                uint32_t a1 = hscale(*(const uint32_t*)&Xs[(rr + 8) * XPH + k0 + 2 * q], hs1[m]);
                uint32_t a2 = hscale(*(const uint32_t*)&Xs[rr * XPH + k0 + 2 * q + 8], hs0[m]);
                uint32_t a3 = hscale(*(const uint32_t*)&Xs[(rr + 8) * XPH + k0 + 2 * q + 8], hs1[m]);
#pragma unroll
                for (int n = 0; n < 4; n++)
                    mma16816(acc[m][n], a0, a1, a2, a3, B0[n], B1[n]);
            }
        }
        __syncthreads();
        if (b + 3 < 8) {
            const __half* wp = Wh + (size_t)kbs[b + 3] * 64 * CI;
            uint32_t dstb = sWs + ((b % 3) * 64 * KP) * 2;
            for (int i = tid; i < WCH; i += 256) {
                int row = i / (CI / 8), c8 = i % (CI / 8);
                cp16(dstb + (row * KP + c8 * 8) * 2, wp + row * CI + c8 * 8);
            }
            CP_COMMIT();
        }
    }

#pragma unroll
    for (int m = 0; m < 2; m++)
#pragma unroll
        for (int h = 0; h < 2; h++) {
            int row = wm * 32 + m * 16 + g + h * 8;
            int slot = slots[row];
            if (slot >= 0) {
                __half2* base = (__half2*)(g_msgh + (size_t)slot * 64 + wn * 32);
#pragma unroll
                for (int n = 0; n < 4; n++)
                    base[(n * 8 + q * 2) >> 1] =
                        __floats2half2_rn(acc[m][n][h * 2], acc[m][n][h * 2 + 1]);
            }
        }
}

// ---------------- layer 1 (CI=1, CO=32): basis recomputed ----------------
__global__ void k_conv1(const float* __restrict__ x, const int* __restrict__ ei,
                        const float* __restrict__ ps, const float* __restrict__ w1, int E) {
    int e = blockIdx.x * 8 + (threadIdx.x >> 5);
    if (e >= E) return;
    int c = threadIdx.x & 31;
    float fr[3];
    int cell;
    basis_of(ps, e, fr, &cell);
    int ix = cell >> 4, iy = (cell >> 2) & 3, iz = cell & 3;
    float acc = 0.0f;
#pragma unroll
    for (int b = 0; b < 8; b++) {
        int kb = (ix + (b & 1)) * 25 + (iy + ((b >> 1) & 1)) * 5 + (iz + ((b >> 2) & 1));
        acc += basis_w(fr, b) * w1[kb * 32 + c];
    }
    g_msgh[(size_t)g_slotE[e] * 32 + c] = __float2half(x[ei[e]] * acc);
}

// ---------------- light reduce (CO=64) ----------------
__global__ void __launch_bounds__(256) k_reduceL(const float* __restrict__ rootb,
                                                 __half* __restrict__ xout, int N) {
    int n = blockIdx.x * 8 + (threadIdx.x >> 5);
    if (n >= N) return;
    int jp = threadIdx.x & 31;
    int s0 = g_dstStart[n], s1 = g_dstStart[n + 1];
    float sx = 0.0f, sy = 0.0f, sx2 = 0.0f, sy2 = 0.0f;
    int r = s0;
    for (; r + 2 <= s1; r += 2) {
        float2 v0 = __half22float2(((const __half2*)(g_msgh + (size_t)r * 64))[jp]);
        float2 v1 = __half22float2(((const __half2*)(g_msgh + (size_t)(r + 1) * 64))[jp]);
        sx += v0.x; sy += v0.y;
        sx2 += v1.x; sy2 += v1.y;
    }
    if (r < s1) {
        float2 v = __half22float2(((const __half2*)(g_msgh + (size_t)r * 64))[jp]);
        sx += v.x; sy += v.y;
    }
    sx += sx2; sy += sy2;
    float inv = 1.0f / (float)max(g_deg[n], 1);
    float2 rb = *(const float2*)&rootb[(size_t)n * 64 + jp * 2];
    ((__half2*)(xout + (size_t)n * 64))[jp] =
        __floats2half2_rn(elu_f(sx * inv + rb.x), elu_f(sy * inv + rb.y));
}

// ---------------- layer-1 reduce (CO=32), root inline ----------------
__global__ void __launch_bounds__(256) k_reduce1(const float* __restrict__ x,
                                                 const float* __restrict__ root1,
                                                 const float* __restrict__ b1,
                                                 __half* __restrict__ xout, int N) {
    int n = blockIdx.x * 16 + (threadIdx.x >> 4);
    if (n >= N) return;
    int jp = threadIdx.x & 15;
    int s0 = g_dstStart[n], s1 = g_dstStart[n + 1];
    float sx = 0.0f, sy = 0.0f;
    for (int r = s0; r < s1; r++) {
        float2 v = __half22float2(((const __half2*)(g_msgh + (size_t)r * 32))[jp]);
        sx += v.x; sy += v.y;
    }
    float inv = 1.0f / (float)max(g_deg[n], 1);
    float xn = x[n];
    float2 rv = *(const float2*)&root1[jp * 2];
    float2 bv = *(const float2*)&b1[jp * 2];
    ((__half2*)(xout + (size_t)n * 32))[jp] =
        __floats2half2_rn(elu_f(sx * inv + xn * rv.x + bv.x), elu_f(sy * inv + xn * rv.y + bv.y));
}

// ---------------- FC GEMM f16: block 64x128, warp 32x32, pipelined ----------------
template <int KD, bool DOELU, bool OUTH>
__global__ void __launch_bounds__(256) k_fc_h(const __half* __restrict__ A,
                                              const __half* __restrict__ Bh,
                                              const float* __restrict__ bias,
                                              void* __restrict__ Cv, int M, int NC) {
    constexpr int APH = 72, BPH = 72;
    constexpr int NIT = KD / 64;
    extern __shared__ char smc[];
    __half* As = (__half*)smc;
    __half* Bs = As + 2 * 64 * APH;
    uint32_t sAs = smem_u32(As), sBs = smem_u32(Bs);
    int rb = blockIdx.x * 64, cb = blockIdx.y * 128;
    int tid = threadIdx.x, wid = tid >> 5, lid = tid & 31;
    int wm = wid >> 2, wn = wid & 3;
    int g = lid >> 2, q = lid & 3;

    auto stage = [&](int it, int buf) {
        int kc = it * 64;
        for (int i = tid; i < 512; i += 256) {
            int row = i >> 3, c8 = i & 7;
            int gr = rb + row;
            cp16z(sAs + (buf * 64 * APH + row * APH + c8 * 8) * 2,
                  A + (size_t)min(gr, M - 1) * KD + kc + c8 * 8, (gr < M) ? 16 : 0);
        }
        for (int i = tid; i < 1024; i += 256) {
            int row = i >> 3, c8 = i & 7;
            cp16(sBs + (buf * 128 * BPH + row * BPH + c8 * 8) * 2,
                 Bh + (size_t)(cb + row) * KD + kc + c8 * 8);
        }
        CP_COMMIT();
    };

    float acc[2][4][4];
#pragma unroll
    for (int m = 0; m < 2; m++)
#pragma unroll
        for (int n = 0; n < 4; n++)
#pragma unroll
            for (int i = 0; i < 4; i++) acc[m][n][i] = 0.0f;

    stage(0, 0);
    if (NIT > 1) stage(1, 1);

#pragma unroll
    for (int it = 0; it < NIT; it++) {
        if (it + 1 < NIT) cp_wait<1>(); else cp_wait<0>();
        __syncthreads();
        const __half* Ab = As + (it & 1) * 64 * APH;
        const __half* Bb = Bs + (it & 1) * 128 * BPH;
#pragma unroll
        for (int ks = 0; ks < 4; ks++) {
            int k0 = ks * 16;
            uint32_t B0[4], B1[4];
#pragma unroll
            for (int n = 0; n < 4; n++) {
                int c = wn * 32 + n * 8 + g;
                B0[n] = *(const uint32_t*)&Bb[c * BPH + k0 + 2 * q];
                B1[n] = *(const uint32_t*)&Bb[c * BPH + k0 + 2 * q + 8];
            }
#pragma unroll
            for (int m = 0; m < 2; m++) {
                int rr = wm * 32 + m * 16 + g;
                uint32_t a0 = *(const uint32_t*)&Ab[rr * APH + k0 + 2 * q];
                uint32_t a1 = *(const uint32_t*)&Ab[(rr + 8) * APH + k0 + 2 * q];
                uint32_t a2 = *(const uint32_t*)&Ab[rr * APH + k0 + 2 * q + 8];
                uint32_t a3 = *(const uint32_t*)&Ab[(rr + 8) * APH + k0 + 2 * q + 8];
#pragma unroll
                for (int n = 0; n < 4; n++)
                    mma16816(acc[m][n], a0, a1, a2, a3, B0[n], B1[n]);
            }
        }
        __syncthreads();
        if (it + 2 < NIT) stage(it + 2, it & 1);
    }

#pragma unroll
    for (int m = 0; m < 2; m++)
#pragma unroll
        for (int h = 0; h < 2; h++) {
            int gr = rb + wm * 32 + m * 16 + g + h * 8;
            if (gr >= M) continue;
#pragma unroll
            for (int n = 0; n < 4; n++) {
                int col = cb + wn * 32 + n * 8 + q * 2;
                float v0 = acc[m][n][h * 2] + bias[col];
                float v1 = acc[m][n][h * 2 + 1] + bias[col + 1];
                if (DOELU) { v0 = elu_f(v0); v1 = elu_f(v1); }
                if (OUTH) {
                    *(__half2*)((__half*)Cv + (size_t)gr * NC + col) = __floats2half2_rn(v0, v1);
                } else {
                    *(float2*)((float*)Cv + (size_t)gr * NC + col) = make_float2(v0, v1);
                }
            }
        }
}

// ---------------- log_softmax ----------------
__global__ void k_lsm(float* __restrict__ out) {
    __shared__ float red[256];
    int n = blockIdx.x;
    float* row = out + (size_t)n * 1024;
    int tid = threadIdx.x;
    float v[4];
    float m = -INFINITY;
#pragma unroll
    for (int i = 0; i < 4; i++) { v[i] = row[tid + 256 * i]; m = fmaxf(m, v[i]); }
    red[tid] = m;
    __syncthreads();
    for (int off = 128; off; off >>= 1) {
        if (tid < off) red[tid] = fmaxf(red[tid], red[tid + off]);
        __syncthreads();
    }
    m = red[0];
    __syncthreads();
    float s = 0.0f;
#pragma unroll
    for (int i = 0; i < 4; i++) s += __expf(v[i] - m);
    red[tid] = s;
    __syncthreads();
    for (int off = 128; off; off >>= 1) {
        if (tid < off) red[tid] += red[tid + off];
        __syncthreads();
    }
    float l = m + __logf(red[0]);
#pragma unroll
    for (int i = 0; i < 4; i++) row[tid + 256 * i] = v[i] - l;
}

// ---------------- launcher ----------------
extern "C" void kernel_launch(void* const* d_in, const int* in_sizes, int n_in,
                              void* d_out, int out_size) {
    const float* x      = (const float*)d_in[0];
    const int*   ei     = (const int*)d_in[1];
    const float* pseudo = (const float*)d_in[2];
    const float *w[6], *root[6], *bias[6];
    for (int i = 0; i < 6; i++) {
        w[i]    = (const float*)d_in[3 + 3 * i];
        root[i] = (const float*)d_in[4 + 3 * i];
        bias[i] = (const float*)d_in[5 + 3 * i];
    }
    const float* fc1b = (const float*)d_in[22];
    const float* fc2b = (const float*)d_in[24];
    float* out = (float*)d_out;

    int N = in_sizes[0];
    int E = in_sizes[1] / 2;

    int eg = (E + 255) / 256;
    int ng = (N + 255) / 256;
    int nchunksUB = (E + 127) / 128 + 64;
    int nb64 = (N + 63) / 64;
    int cgrid = nchunksUB + nb64;

    __half* hAh = nullptr;  cudaGetSymbolAddress((void**)&hAh, g_hAh);
    __half* hBh = nullptr;  cudaGetSymbolAddress((void**)&hBh, g_hBh);
    __half* h256h = nullptr; cudaGetSymbolAddress((void**)&h256h, g_h256h);
    float*  rtb = nullptr;  cudaGetSymbolAddress((void**)&rtb, g_root);
    __half* wh = nullptr;   cudaGetSymbolAddress((void**)&wh, g_wh);

    constexpr int CSM64 = 512 + 4096 + (128 * 72 + 3 * 64 * 72) * 2;   // 50688
    constexpr int CSM32 = 512 + 4096 + (128 * 40 + 3 * 64 * 40) * 2;   // 30208
    constexpr int FSM   = (2 * 64 * 72 + 2 * 128 * 72) * 2;            // 55296
    cudaFuncSetAttribute(k_convroot<64>, cudaFuncAttributeMaxDynamicSharedMemorySize, CSM64);
    cudaFuncSetAttribute(k_convroot<32>, cudaFuncAttributeMaxDynamicSharedMemorySize, CSM32);
    cudaFuncSetAttribute((const void*)k_fc_h<64, true, true>, cudaFuncAttributeMaxDynamicSharedMemorySize, FSM);
    cudaFuncSetAttribute((const void*)k_fc_h<256, false, false>, cudaFuncAttributeMaxDynamicSharedMemorySize, FSM);

    k_init<<<ng, 256>>>(N);
    k_prep<<<eg + 160, 256>>>(ei, pseudo, E, eg,
                              w[1], w[2], w[3], w[4], w[5],
                              root[1], root[2], root[3], root[4], root[5],
                              (const float*)d_in[21], (const float*)d_in[23]);
    k_scan<<<1, 1024>>>(N, E);
    k_scatter<<<eg, 256>>>(ei, pseudo, E);

    // layer 1: 1 -> 32
    k_conv1<<<(E + 7) / 8, 256>>>(x, ei, pseudo, w[0], E);
    k_reduce1<<<(N + 15) / 16, 256>>>(x, root[0], bias[0], hAh, N);
    // layer 2: 32 -> 64
    k_convroot<32><<<cgrid, 256, CSM32>>>(hAh, wh + OFF_W2, wh + OFF_R2, bias[1], rtb, N, nb64);
    k_reduceL<<<(N + 7) / 8, 256>>>(rtb, hBh, N);
    // layers 3-6: 64 -> 64
    k_convroot<64><<<cgrid, 256, CSM64>>>(hBh, wh + OFF_W3, wh + OFF_R3, bias[2], rtb, N, nb64);
    k_reduceL<<<(N + 7) / 8, 256>>>(rtb, hAh, N);

    k_convroot<64><<<cgrid, 256, CSM64>>>(hAh, wh + OFF_W4, wh + OFF_R4, bias[3], rtb, N, nb64);
    k_reduceL<<<(N + 7) / 8, 256>>>(rtb, hBh, N);

    k_convroot<64><<<cgrid, 256, CSM64>>>(hBh, wh + OFF_W5, wh + OFF_R5, bias[4], rtb, N, nb64);
    k_reduceL<<<(N + 7) / 8, 256>>>(rtb, hAh, N);

    k_convroot<64><<<cgrid, 256, CSM64>>>(hAh, wh + OFF_W6, wh + OFF_R6, bias[5], rtb, N, nb64);
    k_reduceL<<<(N + 7) / 8, 256>>>(rtb, hBh, N);

    // fc1: [N,64] @ [64,256] + ELU -> half
    k_fc_h<64, true, true><<<dim3(nb64, 2), 256, FSM>>>(hBh, wh + OFF_FC1, fc1b, h256h, N, 256);
    // fc2: [N,256] @ [256,1024] -> fp32 logits
    k_fc_h<256, false, false><<<dim3(nb64, 8), 256, FSM>>>(h256h, wh + OFF_FC2, fc2b, out, N, 1024);
    // log_softmax in place
    k_lsm<<<N, 256>>>(out);
}